// round 3
// baseline (speedup 1.0000x reference)
#include <cuda_runtime.h>
#include <math.h>

// ---------------- problem dims (fixed) ----------------
#define BDIM   8
#define TDIM   4096
#define HEADSN 8
#define ES     64
#define EMBN   512
#define MF     32
#define HIDN   2048
#define NTOK   (BDIM*TDIM)        // 32768
#define NROWH  (NTOK*HEADSN)      // 262144

// ---------------- scratch (device globals: no allocation allowed) ----------------
__device__ float g_h   [NTOK*EMBN];     // LN1 out / LN2 out (reused)
__device__ float g_kqv [NROWH*192];     // per (token,head): k|q|v
__device__ float g_kp  [NROWH*MF];      // [b*8+h][t][m]
__device__ float g_qp  [NROWH*MF];      // [bt*8+h][m]  (token-major)
__device__ float g_v   [NROWH*ES];      // [b*8+h][t][e]
__device__ float g_ks  [64*MF];
__device__ float g_kptv[64*ES*MF];      // [bh][e][m]
__device__ float g_y   [NTOK*EMBN];
__device__ float g_x1  [NTOK*EMBN];     // x + attn (residual)
__device__ float g_hid [NTOK*HIDN];

// ---------------- f32x2 packed-FMA helpers (Blackwell FFMA2) ----------------
__device__ __forceinline__ unsigned long long pk2(float a) {
    unsigned long long r; unsigned int u = __float_as_uint(a);
    asm("mov.b64 %0, {%1, %1};" : "=l"(r) : "r"(u));
    return r;
}
__device__ __forceinline__ void fma2(unsigned long long& d, unsigned long long a, unsigned long long b) {
    asm("fma.rn.f32x2 %0, %1, %2, %0;" : "+l"(d) : "l"(a), "l"(b));
}
__device__ __forceinline__ void upk2(unsigned long long v, float& lo, float& hi) {
    unsigned int a, b;
    asm("mov.b64 {%0, %1}, %2;" : "=r"(a), "=r"(b) : "l"(v));
    lo = __uint_as_float(a); hi = __uint_as_float(b);
}

__device__ __forceinline__ float gelu_f(float v) {
    return 0.5f * v * (1.0f + erff(v * 0.7071067811865476f));
}

// ---------------- LayerNorm: warp per token ----------------
__global__ void ln_kernel(const float* __restrict__ x, const float* __restrict__ g,
                          const float* __restrict__ b, float* __restrict__ out) {
    int wid = threadIdx.x >> 5, lane = threadIdx.x & 31;
    long row = (long)blockIdx.x * 8 + wid;
    const float4* xr = (const float4*)(x + row * EMBN);
    float4 v[4];
    float s = 0.f, sq = 0.f;
#pragma unroll
    for (int j = 0; j < 4; j++) {
        v[j] = xr[lane + 32 * j];
        s  += v[j].x + v[j].y + v[j].z + v[j].w;
        sq += v[j].x*v[j].x + v[j].y*v[j].y + v[j].z*v[j].z + v[j].w*v[j].w;
    }
#pragma unroll
    for (int o = 16; o; o >>= 1) {
        s  += __shfl_xor_sync(0xffffffffu, s,  o);
        sq += __shfl_xor_sync(0xffffffffu, sq, o);
    }
    float mu = s * (1.0f / EMBN);
    float var = sq * (1.0f / EMBN) - mu * mu;
    float rs = rsqrtf(var + 1e-5f);
    float4* orow = (float4*)(out + row * EMBN);
#pragma unroll
    for (int j = 0; j < 4; j++) {
        int fi = lane + 32 * j;
        float4 g4 = ((const float4*)g)[fi];
        float4 b4 = ((const float4*)b)[fi];
        float4 o4;
        o4.x = (v[j].x - mu) * rs * g4.x + b4.x;
        o4.y = (v[j].y - mu) * rs * g4.y + b4.y;
        o4.z = (v[j].z - mu) * rs * g4.z + b4.z;
        o4.w = (v[j].w - mu) * rs * g4.w + b4.w;
        orow[fi] = o4;
    }
}

// ---------------- SGEMM: C[m][n] = sum_k A[m][k]*W[n][k] (+epilogue) ----------------
// 128x128 tile, BK=8, 256 threads, 8x8 microtile via f32x2 packed FMA, double-buffered.
// EPI: 0 = +bias ; 1 = gelu(+bias) ; 2 = +bias +resid
template<int EPI>
__global__ __launch_bounds__(256, 2)
void gemm_kernel(const float* __restrict__ A, const float* __restrict__ W,
                 const float* __restrict__ bias, const float* __restrict__ resid,
                 float* __restrict__ C, int N, int K) {
    __shared__ __align__(16) float As[2][8][128];
    __shared__ __align__(16) float Bs[2][8][128];
    int tid = threadIdx.x;
    int m0 = blockIdx.x * 128;
    int n0 = blockIdx.y * 128;

    int lr = tid >> 1;            // 0..127
    int lc = (tid & 1) * 4;       // 0 or 4
    const float* Ap = A + (size_t)(m0 + lr) * K + lc;
    int wr = n0 + lr;
    const float* Wp = W + (size_t)wr * K + lc;
    bool wv = wr < N;

    float4 a4 = *(const float4*)Ap;
    float4 b4 = wv ? *(const float4*)Wp : make_float4(0.f, 0.f, 0.f, 0.f);
    As[0][lc+0][lr] = a4.x; As[0][lc+1][lr] = a4.y; As[0][lc+2][lr] = a4.z; As[0][lc+3][lr] = a4.w;
    Bs[0][lc+0][lr] = b4.x; Bs[0][lc+1][lr] = b4.y; Bs[0][lc+2][lr] = b4.z; Bs[0][lc+3][lr] = b4.w;
    __syncthreads();

    unsigned long long acc[8][4];
#pragma unroll
    for (int i = 0; i < 8; i++)
#pragma unroll
        for (int j = 0; j < 4; j++) acc[i][j] = 0ull;

    int tx = tid & 15, ty = tid >> 4;
    int KT = K >> 3;
    int buf = 0;
    for (int kt = 0; kt < KT; kt++) {
        bool more = (kt + 1 < KT);
        if (more) {
            a4 = *(const float4*)(Ap + (kt + 1) * 8);
            b4 = wv ? *(const float4*)(Wp + (kt + 1) * 8) : make_float4(0.f, 0.f, 0.f, 0.f);
        }
#pragma unroll
        for (int kk = 0; kk < 8; kk++) {
            float4 am0 = *(const float4*)&As[buf][kk][ty * 4];
            float4 am1 = *(const float4*)&As[buf][kk][64 + ty * 4];
            ulonglong2 bb0 = *(const ulonglong2*)&Bs[buf][kk][tx * 4];
            ulonglong2 bb1 = *(const ulonglong2*)&Bs[buf][kk][64 + tx * 4];
            unsigned long long bp0 = bb0.x, bp1 = bb0.y, bp2 = bb1.x, bp3 = bb1.y;
            float am[8] = {am0.x, am0.y, am0.z, am0.w, am1.x, am1.y, am1.z, am1.w};
#pragma unroll
            for (int mi = 0; mi < 8; mi++) {
                unsigned long long a2 = pk2(am[mi]);
                fma2(acc[mi][0], a2, bp0);
                fma2(acc[mi][1], a2, bp1);
                fma2(acc[mi][2], a2, bp2);
                fma2(acc[mi][3], a2, bp3);
            }
        }
        if (more) {
            int nb = buf ^ 1;
            As[nb][lc+0][lr] = a4.x; As[nb][lc+1][lr] = a4.y; As[nb][lc+2][lr] = a4.z; As[nb][lc+3][lr] = a4.w;
            Bs[nb][lc+0][lr] = b4.x; Bs[nb][lc+1][lr] = b4.y; Bs[nb][lc+2][lr] = b4.z; Bs[nb][lc+3][lr] = b4.w;
        }
        __syncthreads();
        buf ^= 1;
    }

    // epilogue
#pragma unroll
    for (int mi = 0; mi < 8; mi++) {
        int mrow = m0 + ((mi < 4) ? (ty * 4 + mi) : (64 + ty * 4 + (mi - 4)));
        float* crow = C + (size_t)mrow * N;
        const float* rrow = (EPI == 2) ? (resid + (size_t)mrow * N) : nullptr;
#pragma unroll
        for (int nj = 0; nj < 4; nj++) {
            int n = n0 + ((nj < 2) ? (tx * 4 + nj * 2) : (64 + tx * 4 + (nj - 2) * 2));
            if (n < N) {
                float lo, hi;
                upk2(acc[mi][nj], lo, hi);
                lo += bias[n];
                hi += bias[n + 1];
                if (EPI == 1) { lo = gelu_f(lo); hi = gelu_f(hi); }
                if (EPI == 2) { lo += rrow[n]; hi += rrow[n + 1]; }
                *(float2*)(crow + n) = make_float2(lo, hi);
            }
        }
    }
}

// ---------------- prm_exp + split k/q/v : warp per (token,head) row ----------------
__global__ void prm_kernel(const float* __restrict__ kqv, const float* __restrict__ w,
                           float* __restrict__ kp, float* __restrict__ qp,
                           float* __restrict__ vout) {
    __shared__ float w_s[32 * 65];
    __shared__ float z_s[8][128];
    int tid = threadIdx.x;
    for (int i = tid; i < MF * ES; i += 256)
        w_s[(i >> 6) * 65 + (i & 63)] = w[i];

    int wid = tid >> 5, lane = tid & 31;
    long row = (long)blockIdx.x * 8 + wid;          // = bt*8 + h
    const float* r = kqv + row * 192;
    float k0 = r[lane],       k1 = r[lane + 32];
    float q0 = r[lane + 64],  q1 = r[lane + 96];
    float v0 = r[lane + 128], v1 = r[lane + 160];

    int  h  = (int)(row & 7);
    long bt = row >> 3;
    int  b  = (int)(bt >> 12);
    int  t  = (int)(bt & 4095);

    long vrow = ((long)(b * 8 + h) * TDIM + t) * ES;
    vout[vrow + lane] = v0;
    vout[vrow + 32 + lane] = v1;

    z_s[wid][lane]      = k0;  z_s[wid][lane + 32] = k1;
    z_s[wid][64 + lane] = q0;  z_s[wid][96 + lane] = q1;

    float sk = k0 * k0 + k1 * k1;
    float sq = q0 * q0 + q1 * q1;
#pragma unroll
    for (int o = 16; o; o >>= 1) {
        sk += __shfl_xor_sync(0xffffffffu, sk, o);
        sq += __shfl_xor_sync(0xffffffffu, sq, o);
    }
    float xdk = 0.5f * sk, xdq = 0.5f * sq;
    __syncthreads();

    const float* wm = &w_s[lane * 65];
    float wk = 0.f, wq = 0.f;
#pragma unroll 8
    for (int e = 0; e < 64; e++) {
        float we = wm[e];
        wk += we * z_s[wid][e];
        wq += we * z_s[wid][64 + e];
    }
    const float rsM = 0.17677669529663687f;   // 1/sqrt(32)
    float kpv = expf(wk - xdk) * rsM;
    float qpv = expf(wq - xdq) * rsM;
    kp[((long)(b * 8 + h) * TDIM + t) * MF + lane] = kpv;
    qp[row * MF + lane] = qpv;
}

// ---------------- zero scratch for reductions ----------------
__global__ void zero_kernel(float* __restrict__ kptv, float* __restrict__ ks) {
    int i = blockIdx.x * 256 + threadIdx.x;
    if (i < 64 * ES * MF) kptv[i] = 0.f;
    if (i < 64 * MF) ks[i] = 0.f;
}

// ---------------- kptv[bh][e][m] = sum_t v[bh][t][e]*kp[bh][t][m]; ks = sum_t kp ----------------
__global__ void kptv_kernel(const float* __restrict__ kp, const float* __restrict__ v,
                            float* __restrict__ kptv, float* __restrict__ ks) {
    int bh = blockIdx.x, seg = blockIdx.y;     // 64 x 8, 512 tokens per segment
    const float* kpb = kp + ((long)bh * TDIM + seg * 512) * MF;
    const float* vb  = v  + ((long)bh * TDIM + seg * 512) * ES;
    __shared__ float kc[16][32];
    __shared__ float vc[16][64];
    int tid = threadIdx.x;
    int m = tid & 31, eg = tid >> 5;            // eg 0..7 -> e base eg*8
    float acc[8] = {0.f, 0.f, 0.f, 0.f, 0.f, 0.f, 0.f, 0.f};
    float ksa = 0.f;
    for (int c = 0; c < 32; c++) {
        __syncthreads();
#pragma unroll
        for (int i = 0; i < 2; i++) {
            int idx = tid + i * 256;
            kc[idx >> 5][idx & 31] = kpb[c * 512 + idx];
        }
#pragma unroll
        for (int i = 0; i < 4; i++) {
            int idx = tid + i * 256;
            vc[idx >> 6][idx & 63] = vb[c * 1024 + idx];
        }
        __syncthreads();
#pragma unroll
        for (int tt = 0; tt < 16; tt++) {
            float kv = kc[tt][m];
            if (eg == 0) ksa += kv;
#pragma unroll
            for (int j = 0; j < 8; j++) acc[j] += vc[tt][eg * 8 + j] * kv;
        }
    }
#pragma unroll
    for (int j = 0; j < 8; j++)
        atomicAdd(&kptv[(long)bh * (ES * MF) + (eg * 8 + j) * MF + m], acc[j]);
    if (eg == 0) atomicAdd(&ks[bh * MF + m], ksa);
}

// ---------------- y = (qp @ kptv^T)/D : warp per token, 4 heads per block ----------------
__global__ void y_kernel(const float* __restrict__ qp, const float* __restrict__ kptv,
                         const float* __restrict__ ks, float* __restrict__ y) {
    int tset = blockIdx.x, b = blockIdx.y, hh = blockIdx.z;  // heads hh*4 .. +3
    __shared__ float kv_s[4 * 64 * 33];
    __shared__ float ks_s[4 * 32];
    int tid = threadIdx.x;
    for (int i = tid; i < 4 * 64 * 32; i += 256) {
        int h = i >> 11, e = (i >> 5) & 63, m = i & 31;
        kv_s[(h * 64 + e) * 33 + m] = kptv[((long)(b * 8 + hh * 4 + h) * 64 + e) * 32 + m];
    }
    if (tid < 128) ks_s[tid] = ks[(b * 8 + hh * 4) * 32 + tid];
    __syncthreads();

    int wid = tid >> 5, lane = tid & 31;
    int t = tset * 8 + wid;
    long row = (long)b * TDIM + t;
    const float* qpp = qp + row * (HEADSN * MF) + hh * 128;
    float qpr[4];
#pragma unroll
    for (int j = 0; j < 4; j++) qpr[j] = qpp[j * 32 + lane];
    float* yr = y + row * EMBN + hh * 256;
#pragma unroll
    for (int h = 0; h < 4; h++) {
        float d = qpr[h] * ks_s[h * 32 + lane];
#pragma unroll
        for (int o = 16; o; o >>= 1) d += __shfl_xor_sync(0xffffffffu, d, o);
        float invd = 1.0f / d;
        const float* kvh = &kv_s[h * 64 * 33];
        float a0 = 0.f, a1 = 0.f;
#pragma unroll 8
        for (int m = 0; m < 32; m++) {
            float qm = __shfl_sync(0xffffffffu, qpr[h], m);
            a0 += kvh[lane * 33 + m] * qm;
            a1 += kvh[(lane + 32) * 33 + m] * qm;
        }
        yr[h * 64 + lane]      = a0 * invd;
        yr[h * 64 + 32 + lane] = a1 * invd;
    }
}

// ---------------- launcher ----------------
extern "C" void kernel_launch(void* const* d_in, const int* in_sizes, int n_in,
                              void* d_out, int out_size) {
    const float* x      = (const float*)d_in[0];
    const float* w      = (const float*)d_in[1];
    const float* kqv_w  = (const float*)d_in[2];
    const float* kqv_b  = (const float*)d_in[3];
    const float* proj_w = (const float*)d_in[4];
    const float* proj_b = (const float*)d_in[5];
    const float* ln1_g  = (const float*)d_in[6];
    const float* ln1_b  = (const float*)d_in[7];
    const float* ln2_g  = (const float*)d_in[8];
    const float* ln2_b  = (const float*)d_in[9];
    const float* mlp_w1 = (const float*)d_in[10];
    const float* mlp_b1 = (const float*)d_in[11];
    const float* mlp_w2 = (const float*)d_in[12];
    const float* mlp_b2 = (const float*)d_in[13];
    float* out = (float*)d_out;

    float *ph, *pkqv, *pkp, *pqp, *pv, *pks, *pkptv, *py, *px1, *phid;
    cudaGetSymbolAddress((void**)&ph,    g_h);
    cudaGetSymbolAddress((void**)&pkqv,  g_kqv);
    cudaGetSymbolAddress((void**)&pkp,   g_kp);
    cudaGetSymbolAddress((void**)&pqp,   g_qp);
    cudaGetSymbolAddress((void**)&pv,    g_v);
    cudaGetSymbolAddress((void**)&pks,   g_ks);
    cudaGetSymbolAddress((void**)&pkptv, g_kptv);
    cudaGetSymbolAddress((void**)&py,    g_y);
    cudaGetSymbolAddress((void**)&px1,   g_x1);
    cudaGetSymbolAddress((void**)&phid,  g_hid);

    // 1) LN1
    ln_kernel<<<NTOK / 8, 256>>>(x, ln1_g, ln1_b, ph);
    // 2) kqv GEMM: [262144,64] @ [192,64]^T + bias
    gemm_kernel<0><<<dim3(NROWH / 128, 2), 256>>>(ph, kqv_w, kqv_b, nullptr, pkqv, 192, 64);
    // 3) random features + v scatter
    prm_kernel<<<NROWH / 8, 256>>>(pkqv, w, pkp, pqp, pv);
    // 4) zero reduction scratch
    zero_kernel<<<(64 * ES * MF + 255) / 256, 256>>>(pkptv, pks);
    // 5) kptv + ks reduction over T
    kptv_kernel<<<dim3(64, 8), 256>>>(pkp, pv, pkptv, pks);
    // 6) y = (qp @ kptv)/D
    y_kernel<<<dim3(TDIM / 8, BDIM, 2), 256>>>(pqp, pkptv, pks, py);
    // 7) proj GEMM + bias + residual(x) -> x1
    gemm_kernel<2><<<dim3(NTOK / 128, EMBN / 128), 256>>>(py, proj_w, proj_b, x, px1, EMBN, EMBN);
    // 8) LN2
    ln_kernel<<<NTOK / 8, 256>>>(px1, ln2_g, ln2_b, ph);
    // 9) MLP1 GEMM + bias + gelu -> hid
    gemm_kernel<1><<<dim3(NTOK / 128, HIDN / 128), 256>>>(ph, mlp_w1, mlp_b1, nullptr, phid, HIDN, EMBN);
    // 10) MLP2 GEMM + bias + residual(x1) -> out
    gemm_kernel<2><<<dim3(NTOK / 128, EMBN / 128), 256>>>(phid, mlp_w2, mlp_b2, px1, out, EMBN, HIDN);
}

// round 8
// speedup vs baseline: 1.8912x; 1.8912x over previous
#include <cuda_runtime.h>
#include <cuda_bf16.h>
#include <math.h>
#include <stdint.h>

// ---------------- problem dims (fixed) ----------------
#define BDIM   8
#define TDIM   4096
#define HEADSN 8
#define ES     64
#define EMBN   512
#define MF     32
#define HIDN   2048
#define NTOK   (BDIM*TDIM)        // 32768
#define NROWH  (NTOK*HEADSN)      // 262144

// ---------------- scratch (device globals) ----------------
__device__ float g_h   [NTOK*EMBN];
__device__ float g_kqv [NROWH*192];
__device__ float g_kp  [NROWH*MF];
__device__ float g_qp  [NROWH*MF];
__device__ float g_v   [NROWH*ES];
__device__ float g_ks  [64*MF];
__device__ float g_kptv[64*ES*MF];
__device__ float g_x1  [NTOK*EMBN];

__device__ __nv_bfloat16 g_y_hi [NTOK*EMBN];
__device__ __nv_bfloat16 g_y_lo [NTOK*EMBN];
__device__ __nv_bfloat16 g_h2_hi[NTOK*EMBN];
__device__ __nv_bfloat16 g_h2_lo[NTOK*EMBN];
__device__ __nv_bfloat16 g_hd_hi[NTOK*HIDN];
__device__ __nv_bfloat16 g_hd_lo[NTOK*HIDN];

__device__ __nv_bfloat16 g_pw_hi[EMBN*EMBN];
__device__ __nv_bfloat16 g_pw_lo[EMBN*EMBN];
__device__ __nv_bfloat16 g_w1_hi[HIDN*EMBN];
__device__ __nv_bfloat16 g_w1_lo[HIDN*EMBN];
__device__ __nv_bfloat16 g_w2_hi[EMBN*HIDN];
__device__ __nv_bfloat16 g_w2_lo[EMBN*HIDN];

// ---------------- helpers ----------------
__device__ __forceinline__ uint32_t smem_u32(const void* p) {
    uint32_t a;
    asm("{ .reg .u64 t; cvta.to.shared.u64 t, %1; cvt.u32.u64 %0, t; }" : "=r"(a) : "l"(p));
    return a;
}
__device__ __forceinline__ void cp16(uint32_t saddr, const void* g) {
    asm volatile("cp.async.cg.shared.global [%0], [%1], 16;" :: "r"(saddr), "l"(g) : "memory");
}
__device__ __forceinline__ void ldsm4(uint32_t* r, uint32_t addr) {
    asm volatile("ldmatrix.sync.aligned.m8n8.x4.shared.b16 {%0,%1,%2,%3}, [%4];"
        : "=r"(r[0]), "=r"(r[1]), "=r"(r[2]), "=r"(r[3]) : "r"(addr));
}
__device__ __forceinline__ void hmma(float* d, const uint32_t* a, const uint32_t* b) {
    asm volatile("mma.sync.aligned.m16n8k16.row.col.f32.bf16.bf16.f32 "
        "{%0,%1,%2,%3}, {%4,%5,%6,%7}, {%8,%9}, {%0,%1,%2,%3};"
        : "+f"(d[0]), "+f"(d[1]), "+f"(d[2]), "+f"(d[3])
        : "r"(a[0]), "r"(a[1]), "r"(a[2]), "r"(a[3]), "r"(b[0]), "r"(b[1]));
}
__device__ __forceinline__ float gelu_f(float v) {
    return 0.5f * v * (1.0f + erff(v * 0.7071067811865476f));
}
__device__ __forceinline__ void split_bf16(float v, __nv_bfloat16& hi, __nv_bfloat16& lo) {
    hi = __float2bfloat16(v);
    lo = __float2bfloat16(v - __bfloat162float(hi));
}
// f32x2 packed FMA
__device__ __forceinline__ unsigned long long pk2(float a) {
    unsigned long long r; unsigned int u = __float_as_uint(a);
    asm("mov.b64 %0, {%1, %1};" : "=l"(r) : "r"(u));
    return r;
}
__device__ __forceinline__ void fma2(unsigned long long& d, unsigned long long a, unsigned long long b) {
    asm("fma.rn.f32x2 %0, %1, %2, %0;" : "+l"(d) : "l"(a), "l"(b));
}
__device__ __forceinline__ void upk2(unsigned long long v, float& lo, float& hi) {
    unsigned int a, b;
    asm("mov.b64 {%0, %1}, %2;" : "=r"(a), "=r"(b) : "l"(v));
    lo = __uint_as_float(a); hi = __uint_as_float(b);
}

// ================= HMMA split-bf16 GEMM =================
// C[m][n] = sum_k A[m][k]*W[n][k]; A,W given as bf16 hi/lo pairs.
// CTA tile 128x128, BK=32, STAGES=4, 256 threads, warp tile 32x64.
// EPI 1: o_hi/o_lo = bf16split(gelu(acc+bias)); EPI 2: outf = acc+bias+resid.
#define MM_STAGES 4
#define MM_STAGE_BYTES 32768     // 4 matrices * 128 rows * 64B
#define MM_SMEM (MM_STAGES * MM_STAGE_BYTES)

__device__ __forceinline__ uint32_t swz(int row, int chunk) {
    return (uint32_t)(row * 64 + ((chunk ^ ((row >> 1) & 3)) << 4));
}
__device__ __forceinline__ uint32_t addrA(uint32_t base, int lane, int ks) {
    int grp = lane >> 3;
    int row = (lane & 7) + ((grp & 1) << 3);
    int chunk = (ks << 1) + (grp >> 1);
    return base + swz(row, chunk);
}
__device__ __forceinline__ uint32_t addrB(uint32_t base, int lane, int ks) {
    int grp = lane >> 3;
    int row = (lane & 7) + ((grp >> 1) << 3);
    int chunk = (ks << 1) + (grp & 1);
    return base + swz(row, chunk);
}

template<int EPI>
__global__ void __launch_bounds__(256, 1)
mm_gemm(const __nv_bfloat16* __restrict__ a_hi, const __nv_bfloat16* __restrict__ a_lo,
        const __nv_bfloat16* __restrict__ w_hi, const __nv_bfloat16* __restrict__ w_lo,
        const float* __restrict__ bias, const float* __restrict__ resid,
        float* __restrict__ outf, __nv_bfloat16* __restrict__ o_hi, __nv_bfloat16* __restrict__ o_lo,
        int N, int K) {
    extern __shared__ char smem[];
    uint32_t sb = smem_u32(smem);
    int tid = threadIdx.x, wid = tid >> 5, lane = tid & 31;

    // supertile swizzle: 16 M-tiles per group
    int gn = N >> 7;
    int per = 16 * gn;
    int grp_ = blockIdx.x / per, rem = blockIdx.x - grp_ * per;
    int m0 = (grp_ * 16 + (rem & 15)) * 128;
    int n0 = (rem >> 4) * 128;

    const long rsb = (long)K * 2;   // bytes per row
    const char* Ah = (const char*)a_hi + (long)m0 * rsb;
    const char* Al = (const char*)a_lo + (long)m0 * rsb;
    const char* Bh = (const char*)w_hi + (long)n0 * rsb;
    const char* Bl = (const char*)w_lo + (long)n0 * rsb;

    int lrow = tid >> 1;            // 0..127
    int lc0  = (tid & 1) * 2;       // chunk base 0 or 2
    int KT = K >> 5;                // BK=32

    // prologue: fill STAGES-1 stages
#pragma unroll
    for (int s = 0; s < MM_STAGES - 1; s++) {
        uint32_t st = sb + s * MM_STAGE_BYTES;
        long kb2 = (long)s * 64;    // BK*2 bytes
        long go = (long)lrow * rsb + kb2;
#pragma unroll
        for (int j = 0; j < 2; j++) {
            int c = lc0 + j;
            uint32_t sw = swz(lrow, c);
            cp16(st + sw,          Ah + go + c * 16);
            cp16(st + 8192 + sw,   Al + go + c * 16);
            cp16(st + 16384 + sw,  Bh + go + c * 16);
            cp16(st + 24576 + sw,  Bl + go + c * 16);
        }
        asm volatile("cp.async.commit_group;" ::: "memory");
    }

    int warpM = wid & 3, warpN = wid >> 2;
    float acc[2][8][4];
#pragma unroll
    for (int mt = 0; mt < 2; mt++)
#pragma unroll
        for (int nt = 0; nt < 8; nt++)
#pragma unroll
            for (int q = 0; q < 4; q++) acc[mt][nt][q] = 0.f;

    for (int kt = 0; kt < KT; kt++) {
        asm volatile("cp.async.wait_group %0;" :: "n"(MM_STAGES - 2) : "memory");
        __syncthreads();
        // refill oldest stage (consumed at kt-1)
        int pf = kt + MM_STAGES - 1;
        if (pf < KT) {
            uint32_t st = sb + (pf & (MM_STAGES - 1)) * MM_STAGE_BYTES;
            long kb2 = (long)pf * 64;
            long go = (long)lrow * rsb + kb2;
#pragma unroll
            for (int j = 0; j < 2; j++) {
                int c = lc0 + j;
                uint32_t sw = swz(lrow, c);
                cp16(st + sw,          Ah + go + c * 16);
                cp16(st + 8192 + sw,   Al + go + c * 16);
                cp16(st + 16384 + sw,  Bh + go + c * 16);
                cp16(st + 24576 + sw,  Bl + go + c * 16);
            }
        }
        asm volatile("cp.async.commit_group;" ::: "memory");

        uint32_t st = sb + (kt & (MM_STAGES - 1)) * MM_STAGE_BYTES;
        uint32_t aH = st + (warpM * 32) * 64;
        uint32_t aL = aH + 8192;
        uint32_t bH = st + 16384 + (warpN * 64) * 64;
        uint32_t bL = bH + 8192;

#pragma unroll
        for (int ks = 0; ks < 2; ks++) {
            uint32_t ah[2][4], al[2][4], bh[4][4], bl[4][4];
#pragma unroll
            for (int mt = 0; mt < 2; mt++) {
                ldsm4(ah[mt], addrA(aH + mt * 16 * 64, lane, ks));
                ldsm4(al[mt], addrA(aL + mt * 16 * 64, lane, ks));
            }
#pragma unroll
            for (int np = 0; np < 4; np++) {
                ldsm4(bh[np], addrB(bH + np * 16 * 64, lane, ks));
                ldsm4(bl[np], addrB(bL + np * 16 * 64, lane, ks));
            }
#pragma unroll
            for (int nt = 0; nt < 8; nt++) {
                const uint32_t* bhp = &bh[nt >> 1][(nt & 1) * 2];
                const uint32_t* blp = &bl[nt >> 1][(nt & 1) * 2];
#pragma unroll
                for (int mt = 0; mt < 2; mt++) {
                    hmma(acc[mt][nt], ah[mt], bhp);
                    hmma(acc[mt][nt], ah[mt], blp);
                    hmma(acc[mt][nt], al[mt], bhp);
                }
            }
        }
    }

    // ---------------- epilogue ----------------
    int mb = m0 + warpM * 32, nb = n0 + warpN * 64;
    int r = lane >> 2, cq = (lane & 3) * 2;
#pragma unroll
    for (int mt = 0; mt < 2; mt++) {
#pragma unroll
        for (int half = 0; half < 2; half++) {
            long row = mb + mt * 16 + r + half * 8;
#pragma unroll
            for (int nt = 0; nt < 8; nt++) {
                int col = nb + nt * 8 + cq;
                float v0 = acc[mt][nt][half * 2 + 0] + bias[col];
                float v1 = acc[mt][nt][half * 2 + 1] + bias[col + 1];
                if (EPI == 1) {
                    v0 = gelu_f(v0); v1 = gelu_f(v1);
                    __nv_bfloat16 h0, l0, h1, l1;
                    split_bf16(v0, h0, l0); split_bf16(v1, h1, l1);
                    *(__nv_bfloat162*)(o_hi + row * N + col) = __halves2bfloat162(h0, h1);
                    *(__nv_bfloat162*)(o_lo + row * N + col) = __halves2bfloat162(l0, l1);
                } else {
                    float2 rv = *(const float2*)(resid + row * N + col);
                    *(float2*)(outf + row * N + col) = make_float2(v0 + rv.x, v1 + rv.y);
                }
            }
        }
    }
}

// ---------------- weight split: f32 -> bf16 hi/lo ----------------
__global__ void split_kernel(const float* __restrict__ w, __nv_bfloat16* __restrict__ hi,
                             __nv_bfloat16* __restrict__ lo, int n) {
    int i = blockIdx.x * 256 + threadIdx.x;
    if (i < n) {
        __nv_bfloat16 h, l;
        split_bf16(w[i], h, l);
        hi[i] = h; lo[i] = l;
    }
}

// ---------------- LayerNorm (f32 out) ----------------
__global__ void ln_kernel(const float* __restrict__ x, const float* __restrict__ g,
                          const float* __restrict__ b, float* __restrict__ out) {
    int wid = threadIdx.x >> 5, lane = threadIdx.x & 31;
    long row = (long)blockIdx.x * 8 + wid;
    const float4* xr = (const float4*)(x + row * EMBN);
    float4 v[4];
    float s = 0.f, sq = 0.f;
#pragma unroll
    for (int j = 0; j < 4; j++) {
        v[j] = xr[lane + 32 * j];
        s  += v[j].x + v[j].y + v[j].z + v[j].w;
        sq += v[j].x*v[j].x + v[j].y*v[j].y + v[j].z*v[j].z + v[j].w*v[j].w;
    }
#pragma unroll
    for (int o = 16; o; o >>= 1) {
        s  += __shfl_xor_sync(0xffffffffu, s,  o);
        sq += __shfl_xor_sync(0xffffffffu, sq, o);
    }
    float mu = s * (1.0f / EMBN);
    float var = sq * (1.0f / EMBN) - mu * mu;
    float rsv = rsqrtf(var + 1e-5f);
    float4* orow = (float4*)(out + row * EMBN);
#pragma unroll
    for (int j = 0; j < 4; j++) {
        int fi = lane + 32 * j;
        float4 g4 = ((const float4*)g)[fi];
        float4 b4 = ((const float4*)b)[fi];
        float4 o4;
        o4.x = (v[j].x - mu) * rsv * g4.x + b4.x;
        o4.y = (v[j].y - mu) * rsv * g4.y + b4.y;
        o4.z = (v[j].z - mu) * rsv * g4.z + b4.z;
        o4.w = (v[j].w - mu) * rsv * g4.w + b4.w;
        orow[fi] = o4;
    }
}

// ---------------- LayerNorm (bf16 hi/lo out) ----------------
__global__ void ln_split_kernel(const float* __restrict__ x, const float* __restrict__ g,
                                const float* __restrict__ b,
                                __nv_bfloat16* __restrict__ ohi, __nv_bfloat16* __restrict__ olo) {
    int wid = threadIdx.x >> 5, lane = threadIdx.x & 31;
    long row = (long)blockIdx.x * 8 + wid;
    const float4* xr = (const float4*)(x + row * EMBN);
    float4 v[4];
    float s = 0.f, sq = 0.f;
#pragma unroll
    for (int j = 0; j < 4; j++) {
        v[j] = xr[lane + 32 * j];
        s  += v[j].x + v[j].y + v[j].z + v[j].w;
        sq += v[j].x*v[j].x + v[j].y*v[j].y + v[j].z*v[j].z + v[j].w*v[j].w;
    }
#pragma unroll
    for (int o = 16; o; o >>= 1) {
        s  += __shfl_xor_sync(0xffffffffu, s,  o);
        sq += __shfl_xor_sync(0xffffffffu, sq, o);
    }
    float mu = s * (1.0f / EMBN);
    float var = sq * (1.0f / EMBN) - mu * mu;
    float rsv = rsqrtf(var + 1e-5f);
#pragma unroll
    for (int j = 0; j < 4; j++) {
        int fi = lane + 32 * j;
        float4 g4 = ((const float4*)g)[fi];
        float4 b4 = ((const float4*)b)[fi];
        float o0 = (v[j].x - mu) * rsv * g4.x + b4.x;
        float o1 = (v[j].y - mu) * rsv * g4.y + b4.y;
        float o2 = (v[j].z - mu) * rsv * g4.z + b4.z;
        float o3 = (v[j].w - mu) * rsv * g4.w + b4.w;
        __nv_bfloat16 h0,l0,h1,l1,h2,l2,h3,l3;
        split_bf16(o0,h0,l0); split_bf16(o1,h1,l1); split_bf16(o2,h2,l2); split_bf16(o3,h3,l3);
        long base = row * EMBN + fi * 4;
        *(__nv_bfloat162*)(ohi + base)     = __halves2bfloat162(h0, h1);
        *(__nv_bfloat162*)(ohi + base + 2) = __halves2bfloat162(h2, h3);
        *(__nv_bfloat162*)(olo + base)     = __halves2bfloat162(l0, l1);
        *(__nv_bfloat162*)(olo + base + 2) = __halves2bfloat162(l2, l3);
    }
}

// ---------------- FFMA2 SGEMM (kqv): C = A*W^T + bias ----------------
__global__ __launch_bounds__(256, 2)
void gemm_kernel(const float* __restrict__ A, const float* __restrict__ W,
                 const float* __restrict__ bias, float* __restrict__ C, int N, int K) {
    __shared__ __align__(16) float As[2][8][128];
    __shared__ __align__(16) float Bs[2][8][128];
    int tid = threadIdx.x;
    int m0 = blockIdx.x * 128;
    int n0 = blockIdx.y * 128;
    int lr = tid >> 1, lc = (tid & 1) * 4;
    const float* Ap = A + (size_t)(m0 + lr) * K + lc;
    int wr = n0 + lr;
    const float* Wp = W + (size_t)wr * K + lc;
    bool wv = wr < N;
    float4 a4 = *(const float4*)Ap;
    float4 b4 = wv ? *(const float4*)Wp : make_float4(0.f, 0.f, 0.f, 0.f);
    As[0][lc+0][lr] = a4.x; As[0][lc+1][lr] = a4.y; As[0][lc+2][lr] = a4.z; As[0][lc+3][lr] = a4.w;
    Bs[0][lc+0][lr] = b4.x; Bs[0][lc+1][lr] = b4.y; Bs[0][lc+2][lr] = b4.z; Bs[0][lc+3][lr] = b4.w;
    __syncthreads();
    unsigned long long acc[8][4];
#pragma unroll
    for (int i = 0; i < 8; i++)
#pragma unroll
        for (int j = 0; j < 4; j++) acc[i][j] = 0ull;
    int tx = tid & 15, ty = tid >> 4;
    int KT = K >> 3, buf = 0;
    for (int kt = 0; kt < KT; kt++) {
        bool more = (kt + 1 < KT);
        if (more) {
            a4 = *(const float4*)(Ap + (kt + 1) * 8);
            b4 = wv ? *(const float4*)(Wp + (kt + 1) * 8) : make_float4(0.f, 0.f, 0.f, 0.f);
        }
#pragma unroll
        for (int kk = 0; kk < 8; kk++) {
            float4 am0 = *(const float4*)&As[buf][kk][ty * 4];
            float4 am1 = *(const float4*)&As[buf][kk][64 + ty * 4];
            ulonglong2 bb0 = *(const ulonglong2*)&Bs[buf][kk][tx * 4];
            ulonglong2 bb1 = *(const ulonglong2*)&Bs[buf][kk][64 + tx * 4];
            float am[8] = {am0.x, am0.y, am0.z, am0.w, am1.x, am1.y, am1.z, am1.w};
#pragma unroll
            for (int mi = 0; mi < 8; mi++) {
                unsigned long long a2 = pk2(am[mi]);
                fma2(acc[mi][0], a2, bb0.x);
                fma2(acc[mi][1], a2, bb0.y);
                fma2(acc[mi][2], a2, bb1.x);
                fma2(acc[mi][3], a2, bb1.y);
            }
        }
        if (more) {
            int nb = buf ^ 1;
            As[nb][lc+0][lr] = a4.x; As[nb][lc+1][lr] = a4.y; As[nb][lc+2][lr] = a4.z; As[nb][lc+3][lr] = a4.w;
            Bs[nb][lc+0][lr] = b4.x; Bs[nb][lc+1][lr] = b4.y; Bs[nb][lc+2][lr] = b4.z; Bs[nb][lc+3][lr] = b4.w;
        }
        __syncthreads();
        buf ^= 1;
    }
#pragma unroll
    for (int mi = 0; mi < 8; mi++) {
        int mrow = m0 + ((mi < 4) ? (ty * 4 + mi) : (64 + ty * 4 + (mi - 4)));
        float* crow = C + (size_t)mrow * N;
#pragma unroll
        for (int nj = 0; nj < 4; nj++) {
            int n = n0 + ((nj < 2) ? (tx * 4 + nj * 2) : (64 + tx * 4 + (nj - 2) * 2));
            if (n < N) {
                float lo, hi;
                upk2(acc[mi][nj], lo, hi);
                *(float2*)(crow + n) = make_float2(lo + bias[n], hi + bias[n + 1]);
            }
        }
    }
}

// ---------------- prm_exp + split k/q/v ----------------
__global__ void prm_kernel(const float* __restrict__ kqv, const float* __restrict__ w,
                           float* __restrict__ kp, float* __restrict__ qp,
                           float* __restrict__ vout) {
    __shared__ float w_s[32 * 65];
    __shared__ float z_s[8][128];
    int tid = threadIdx.x;
    for (int i = tid; i < MF * ES; i += 256)
        w_s[(i >> 6) * 65 + (i & 63)] = w[i];
    int wid = tid >> 5, lane = tid & 31;
    long row = (long)blockIdx.x * 8 + wid;
    const float* r = kqv + row * 192;
    float k0 = r[lane],       k1 = r[lane + 32];
    float q0 = r[lane + 64],  q1 = r[lane + 96];
    float v0 = r[lane + 128], v1 = r[lane + 160];
    int  h  = (int)(row & 7);
    long bt = row >> 3;
    int  b  = (int)(bt >> 12);
    int  t  = (int)(bt & 4095);
    long vrow = ((long)(b * 8 + h) * TDIM + t) * ES;
    vout[vrow + lane] = v0;
    vout[vrow + 32 + lane] = v1;
    z_s[wid][lane]      = k0;  z_s[wid][lane + 32] = k1;
    z_s[wid][64 + lane] = q0;  z_s[wid][96 + lane] = q1;
    float sk = k0 * k0 + k1 * k1;
    float sq = q0 * q0 + q1 * q1;
#pragma unroll
    for (int o = 16; o; o >>= 1) {
        sk += __shfl_xor_sync(0xffffffffu, sk, o);
        sq += __shfl_xor_sync(0xffffffffu, sq, o);
    }
    float xdk = 0.5f * sk, xdq = 0.5f * sq;
    __syncthreads();
    const float* wm = &w_s[lane * 65];
    float wk = 0.f, wq = 0.f;
#pragma unroll 8
    for (int e = 0; e < 64; e++) {
        float we = wm[e];
        wk += we * z_s[wid][e];
        wq += we * z_s[wid][64 + e];
    }
    const float rsM = 0.17677669529663687f;
    kp[((long)(b * 8 + h) * TDIM + t) * MF + lane] = expf(wk - xdk) * rsM;
    qp[row * MF + lane] = expf(wq - xdq) * rsM;
}

__global__ void zero_kernel(float* __restrict__ kptv, float* __restrict__ ks) {
    int i = blockIdx.x * 256 + threadIdx.x;
    if (i < 64 * ES * MF) kptv[i] = 0.f;
    if (i < 64 * MF) ks[i] = 0.f;
}

__global__ void kptv_kernel(const float* __restrict__ kp, const float* __restrict__ v,
                            float* __restrict__ kptv, float* __restrict__ ks) {
    int bh = blockIdx.x, seg = blockIdx.y;
    const float* kpb = kp + ((long)bh * TDIM + seg * 512) * MF;
    const float* vb  = v  + ((long)bh * TDIM + seg * 512) * ES;
    __shared__ float kc[16][32];
    __shared__ float vc[16][64];
    int tid = threadIdx.x;
    int m = tid & 31, eg = tid >> 5;
    float acc[8] = {0.f, 0.f, 0.f, 0.f, 0.f, 0.f, 0.f, 0.f};
    float ksa = 0.f;
    for (int c = 0; c < 32; c++) {
        __syncthreads();
#pragma unroll
        for (int i = 0; i < 2; i++) {
            int idx = tid + i * 256;
            kc[idx >> 5][idx & 31] = kpb[c * 512 + idx];
        }
#pragma unroll
        for (int i = 0; i < 4; i++) {
            int idx = tid + i * 256;
            vc[idx >> 6][idx & 63] = vb[c * 1024 + idx];
        }
        __syncthreads();
#pragma unroll
        for (int tt = 0; tt < 16; tt++) {
            float kv = kc[tt][m];
            if (eg == 0) ksa += kv;
#pragma unroll
            for (int j = 0; j < 8; j++) acc[j] += vc[tt][eg * 8 + j] * kv;
        }
    }
#pragma unroll
    for (int j = 0; j < 8; j++)
        atomicAdd(&kptv[(long)bh * (ES * MF) + (eg * 8 + j) * MF + m], acc[j]);
    if (eg == 0) atomicAdd(&ks[bh * MF + m], ksa);
}

// ---------------- y = (qp @ kptv^T)/D -> bf16 hi/lo ----------------
__global__ void y_kernel(const float* __restrict__ qp, const float* __restrict__ kptv,
                         const float* __restrict__ ks,
                         __nv_bfloat16* __restrict__ yhi, __nv_bfloat16* __restrict__ ylo) {
    int tset = blockIdx.x, b = blockIdx.y, hh = blockIdx.z;
    __shared__ float kv_s[4 * 64 * 33];
    __shared__ float ks_s[4 * 32];
    int tid = threadIdx.x;
    for (int i = tid; i < 4 * 64 * 32; i += 256) {
        int h = i >> 11, e = (i >> 5) & 63, m = i & 31;
        kv_s[(h * 64 + e) * 33 + m] = kptv[((long)(b * 8 + hh * 4 + h) * 64 + e) * 32 + m];
    }
    if (tid < 128) ks_s[tid] = ks[(b * 8 + hh * 4) * 32 + tid];
    __syncthreads();
    int wid = tid >> 5, lane = tid & 31;
    int t = tset * 8 + wid;
    long row = (long)b * TDIM + t;
    const float* qpp = qp + row * (HEADSN * MF) + hh * 128;
    float qpr[4];
#pragma unroll
    for (int j = 0; j < 4; j++) qpr[j] = qpp[j * 32 + lane];
    long ybase = row * EMBN + hh * 256;
#pragma unroll
    for (int h = 0; h < 4; h++) {
        float d = qpr[h] * ks_s[h * 32 + lane];
#pragma unroll
        for (int o = 16; o; o >>= 1) d += __shfl_xor_sync(0xffffffffu, d, o);
        float invd = 1.0f / d;
        const float* kvh = &kv_s[h * 64 * 33];
        float a0 = 0.f, a1 = 0.f;
#pragma unroll 8
        for (int m = 0; m < 32; m++) {
            float qm = __shfl_sync(0xffffffffu, qpr[h], m);
            a0 += kvh[lane * 33 + m] * qm;
            a1 += kvh[(lane + 32) * 33 + m] * qm;
        }
        float o0 = a0 * invd, o1 = a1 * invd;
        __nv_bfloat16 h0, l0, h1, l1;
        split_bf16(o0, h0, l0); split_bf16(o1, h1, l1);
        yhi[ybase + h * 64 + lane]      = h0;
        ylo[ybase + h * 64 + lane]      = l0;
        yhi[ybase + h * 64 + 32 + lane] = h1;
        ylo[ybase + h * 64 + 32 + lane] = l1;
    }
}

// ---------------- launcher ----------------
extern "C" void kernel_launch(void* const* d_in, const int* in_sizes, int n_in,
                              void* d_out, int out_size) {
    const float* x      = (const float*)d_in[0];
    const float* w      = (const float*)d_in[1];
    const float* kqv_w  = (const float*)d_in[2];
    const float* kqv_b  = (const float*)d_in[3];
    const float* proj_w = (const float*)d_in[4];
    const float* proj_b = (const float*)d_in[5];
    const float* ln1_g  = (const float*)d_in[6];
    const float* ln1_b  = (const float*)d_in[7];
    const float* ln2_g  = (const float*)d_in[8];
    const float* ln2_b  = (const float*)d_in[9];
    const float* mlp_w1 = (const float*)d_in[10];
    const float* mlp_b1 = (const float*)d_in[11];
    const float* mlp_w2 = (const float*)d_in[12];
    const float* mlp_b2 = (const float*)d_in[13];
    float* out = (float*)d_out;

    float *ph, *pkqv, *pkp, *pqp, *pv, *pks, *pkptv, *px1;
    __nv_bfloat16 *pyh, *pyl, *ph2h, *ph2l, *phdh, *phdl;
    __nv_bfloat16 *ppwh, *ppwl, *pw1h, *pw1l, *pw2h, *pw2l;
    cudaGetSymbolAddress((void**)&ph,    g_h);
    cudaGetSymbolAddress((void**)&pkqv,  g_kqv);
    cudaGetSymbolAddress((void**)&pkp,   g_kp);
    cudaGetSymbolAddress((void**)&pqp,   g_qp);
    cudaGetSymbolAddress((void**)&pv,    g_v);
    cudaGetSymbolAddress((void**)&pks,   g_ks);
    cudaGetSymbolAddress((void**)&pkptv, g_kptv);
    cudaGetSymbolAddress((void**)&px1,   g_x1);
    cudaGetSymbolAddress((void**)&pyh,   g_y_hi);
    cudaGetSymbolAddress((void**)&pyl,   g_y_lo);
    cudaGetSymbolAddress((void**)&ph2h,  g_h2_hi);
    cudaGetSymbolAddress((void**)&ph2l,  g_h2_lo);
    cudaGetSymbolAddress((void**)&phdh,  g_hd_hi);
    cudaGetSymbolAddress((void**)&phdl,  g_hd_lo);
    cudaGetSymbolAddress((void**)&ppwh,  g_pw_hi);
    cudaGetSymbolAddress((void**)&ppwl,  g_pw_lo);
    cudaGetSymbolAddress((void**)&pw1h,  g_w1_hi);
    cudaGetSymbolAddress((void**)&pw1l,  g_w1_lo);
    cudaGetSymbolAddress((void**)&pw2h,  g_w2_hi);
    cudaGetSymbolAddress((void**)&pw2l,  g_w2_lo);

    cudaFuncSetAttribute(mm_gemm<1>, cudaFuncAttributeMaxDynamicSharedMemorySize, MM_SMEM);
    cudaFuncSetAttribute(mm_gemm<2>, cudaFuncAttributeMaxDynamicSharedMemorySize, MM_SMEM);

    // weight splits
    split_kernel<<<(EMBN*EMBN + 255)/256, 256>>>(proj_w, ppwh, ppwl, EMBN*EMBN);
    split_kernel<<<(HIDN*EMBN + 255)/256, 256>>>(mlp_w1, pw1h, pw1l, HIDN*EMBN);
    split_kernel<<<(EMBN*HIDN + 255)/256, 256>>>(mlp_w2, pw2h, pw2l, EMBN*HIDN);

    // 1) LN1 -> f32
    ln_kernel<<<NTOK / 8, 256>>>(x, ln1_g, ln1_b, ph);
    // 2) kqv GEMM (FFMA2)
    gemm_kernel<<<dim3(NROWH / 128, 2), 256>>>(ph, kqv_w, kqv_b, pkqv, 192, 64);
    // 3) random features + v scatter
    prm_kernel<<<NROWH / 8, 256>>>(pkqv, w, pkp, pqp, pv);
    // 4) zero reduction scratch
    zero_kernel<<<(64 * ES * MF + 255) / 256, 256>>>(pkptv, pks);
    // 5) kptv + ks
    kptv_kernel<<<dim3(64, 8), 256>>>(pkp, pv, pkptv, pks);
    // 6) y -> bf16 hi/lo
    y_kernel<<<dim3(TDIM / 8, BDIM, 2), 256>>>(pqp, pkptv, pks, pyh, pyl);
    // 7) proj (HMMA) + bias + resid(x) -> x1 (f32)
    mm_gemm<2><<<(NTOK/128) * (EMBN/128), 256, MM_SMEM>>>(
        pyh, pyl, ppwh, ppwl, proj_b, x, px1, nullptr, nullptr, EMBN, EMBN);
    // 8) LN2 -> bf16 hi/lo
    ln_split_kernel<<<NTOK / 8, 256>>>(px1, ln2_g, ln2_b, ph2h, ph2l);
    // 9) MLP1 (HMMA) + bias + gelu -> hid bf16 hi/lo
    mm_gemm<1><<<(NTOK/128) * (HIDN/128), 256, MM_SMEM>>>(
        ph2h, ph2l, pw1h, pw1l, mlp_b1, nullptr, nullptr, phdh, phdl, HIDN, EMBN);
    // 10) MLP2 (HMMA) + bias + resid(x1) -> out
    mm_gemm<2><<<(NTOK/128) * (EMBN/128), 256, MM_SMEM>>>(
        phdh, phdl, pw2h, pw2l, mlp_b2, px1, out, nullptr, nullptr, EMBN, HIDN);
}